// round 9
// baseline (speedup 1.0000x reference)
#include <cuda_runtime.h>
#include <cuda_bf16.h>

// FeatureVectorInteractions: B=4096, N=128, D=64
// out[b] = < sum_i clip(VI0[b,i],0,1)*V0[b,i,:], sum_j clip(VI1[b,j],0,1)*V1[b,j,:] >
//
// Persistent single-wave HBM-streaming kernel. grid = B/4 = 1024 CTAs, each
// handles 4 batches (stride = grid) with a rolling double-buffered mask
// pipeline: batch i+1's VI ints are prefetched (register LDG) during batch
// i's main loop and stashed to smem at the existing barrier. Perfect load
// balance, no wave tail, one cold mask load per CTA. V reads use .cs hints.

#define NROW 128
#define NDIM 64
#define NF4  16            // float4s per row (64 floats / 4)
#define THREADS 256
#define MAXGRID 1024

__device__ __forceinline__ float clip01(int v) {
    return (float)min(max(v, 0), 1);
}

__global__ __launch_bounds__(THREADS, 8)
void fvi_persist(const int* __restrict__ VI0,
                 const int* __restrict__ VI1,
                 const float4* __restrict__ V0,
                 const float4* __restrict__ V1,
                 float* __restrict__ out,
                 int B, int grid)
{
    const int t = threadIdx.x;

    __shared__ float  smM[2][2][NROW];         // [buf][0:mask0 / 1:mask1][row]
    __shared__ float4 s0[THREADS], s1[THREADS];
    __shared__ float  sdot[2];

    int b = blockIdx.x;
    if (b >= B) return;   // whole CTA exits together (grid <= B normally)

    // ---- cold mask load for first batch ----
    if (t < NROW) smM[0][0][t]        = clip01(VI0[b * NROW + t]);
    else          smM[0][1][t - NROW] = clip01(VI1[b * NROW + (t - NROW)]);
    __syncthreads();

    const int q  = t & (NF4 - 1);   // float4 column 0..15
    const int r0 = t >> 4;          // starting row-group 0..15
    int cur = 0;

    for (; b < B; b += grid) {
        const int  bn        = b + grid;
        const bool have_next = (bn < B);

        // prefetch next batch's mask ints (latency hidden by main loop)
        int mbint = 0;
        if (have_next) {
            mbint = (t < NROW) ? __ldg(&VI0[bn * NROW + t])
                               : __ldg(&VI1[bn * NROW + (t - NROW)]);
        }

        // ---- main loop: stream 2 x 8KB of V data, masked accumulate ----
        const float4* p0  = V0 + (size_t)b * (NROW * NF4);
        const float4* p1  = V1 + (size_t)b * (NROW * NF4);
        const float*  m0p = smM[cur][0];
        const float*  m1p = smM[cur][1];

        float4 a0 = make_float4(0.f, 0.f, 0.f, 0.f);
        float4 a1 = make_float4(0.f, 0.f, 0.f, 0.f);

#pragma unroll
        for (int k = 0; k < 8; ++k) {
            const int row = r0 + k * 16;
            float4 x0 = __ldcs(&p0[row * NF4 + q]);
            float4 x1 = __ldcs(&p1[row * NF4 + q]);
            float m0 = m0p[row];
            float m1 = m1p[row];
            a0.x = fmaf(m0, x0.x, a0.x);
            a0.y = fmaf(m0, x0.y, a0.y);
            a0.z = fmaf(m0, x0.z, a0.z);
            a0.w = fmaf(m0, x0.w, a0.w);
            a1.x = fmaf(m1, x1.x, a1.x);
            a1.y = fmaf(m1, x1.y, a1.y);
            a1.z = fmaf(m1, x1.z, a1.z);
            a1.w = fmaf(m1, x1.w, a1.w);
        }

        s0[t] = a0;
        s1[t] = a1;

        // stash prefetched masks into the alternate buffer
        if (have_next) {
            float mb = clip01(mbint);
            if (t < NROW) smM[cur ^ 1][0][t]        = mb;
            else          smM[cur ^ 1][1][t - NROW] = mb;
        }
        __syncthreads();   // B1: s0/s1 + next masks visible

        // ---- epilogue: threads 0..63 reduce dim d = t ----
        if (t < NDIM) {
            const int qq = t >> 2;
            const int j  = t & 3;
            float u0 = 0.f, u1 = 0.f;
#pragma unroll
            for (int g = 0; g < 16; ++g) {
                const float* f0 = (const float*)&s0[g * NF4 + qq];
                const float* f1 = (const float*)&s1[g * NF4 + qq];
                u0 += f0[j];
                u1 += f1[j];
            }
            float prod = u0 * u1;
#pragma unroll
            for (int off = 16; off > 0; off >>= 1)
                prod += __shfl_xor_sync(0xFFFFFFFFu, prod, off);
            if ((t & 31) == 0)
                sdot[t >> 5] = prod;
        }
        __syncthreads();   // B2: sdot ready; s0/s1 free for next batch

        if (t == 0)
            out[b] = sdot[0] + sdot[1];   // safe: next sdot write is behind next B1

        cur ^= 1;
    }
}

extern "C" void kernel_launch(void* const* d_in, const int* in_sizes, int n_in,
                              void* d_out, int out_size)
{
    const int*    VI0 = (const int*)d_in[0];
    const int*    VI1 = (const int*)d_in[1];
    const float4* V0  = (const float4*)d_in[2];
    const float4* V1  = (const float4*)d_in[3];
    float*        out = (float*)d_out;

    const int B    = in_sizes[0] / NROW;          // 4096
    const int grid = (B < MAXGRID) ? B : MAXGRID; // 1024 -> 4 batches/CTA
    fvi_persist<<<grid, THREADS>>>(VI0, VI1, V0, V1, out, B, grid);
}

// round 11
// speedup vs baseline: 1.0454x; 1.0454x over previous
#include <cuda_runtime.h>
#include <cuda_bf16.h>

// FeatureVectorInteractions: B=4096, N=128, D=64
// out[b] = < sum_i clip(VI0[b,i],0,1)*V0[b,i,:], sum_j clip(VI1[b,j],0,1)*V1[b,j,:] >
//
// HBM-streaming reduction. One CTA per TWO batches (b, b+B/2) -> grid=2048,
// which stays ABOVE the 8-CTA/SM x 148-SM = 1184 resident-CTA capacity
// (lesson from the grid=1024 persistent attempt: grid < 1184 starves
// occupancy and DRAM throughput). Batch-2 mask ints are prefetched during
// batch-1's main loop; batch-1's epilogue overlaps batch-2's load issue.
// V0/V1 read with streaming (.cs) hints.

#define NROW 128
#define NDIM 64
#define NF4  16          // float4s per row (64 floats / 4)
#define THREADS 256
#define ROWS_PER_THREAD 8  // 128 rows / 16 row-groups

__device__ __forceinline__ float clip01(int v) {
    return (float)min(max(v, 0), 1);
}

__global__ __launch_bounds__(THREADS, 8)
void fvi_kernel2(const int* __restrict__ VI0,
                 const int* __restrict__ VI1,
                 const float4* __restrict__ V0,
                 const float4* __restrict__ V1,
                 float* __restrict__ out,
                 int half)
{
    const int b0 = blockIdx.x;
    const int b1 = blockIdx.x + half;
    const int t  = threadIdx.x;

    __shared__ float smA0[NROW], smA1[NROW];   // masks batch b0
    __shared__ float smB0[NROW], smB1[NROW];   // masks batch b1
    __shared__ float4 s0[THREADS], s1[THREADS];
    __shared__ float sdotA[2], sdotB[2];

    // ---- Phase 0: masks for b0; prefetch b1 mask int in the same breath ----
    int mbint;
    if (t < NROW) {
        smA0[t] = clip01(VI0[b0 * NROW + t]);
        mbint   = __ldg(&VI0[b1 * NROW + t]);
    } else {
        smA1[t - NROW] = clip01(VI1[b0 * NROW + (t - NROW)]);
        mbint          = __ldg(&VI1[b1 * NROW + (t - NROW)]);
    }
    __syncthreads();

    const int q  = t & (NF4 - 1);   // float4 column 0..15
    const int r0 = t >> 4;          // starting row-group 0..15

    // ---- Phase 1: main loop batch b0 ----
    {
        const float4* p0 = V0 + (size_t)b0 * (NROW * NF4);
        const float4* p1 = V1 + (size_t)b0 * (NROW * NF4);

        float4 a0 = make_float4(0.f, 0.f, 0.f, 0.f);
        float4 a1 = make_float4(0.f, 0.f, 0.f, 0.f);

#pragma unroll
        for (int k = 0; k < ROWS_PER_THREAD; ++k) {
            const int row = r0 + k * 16;
            float4 x0 = __ldcs(&p0[row * NF4 + q]);
            float4 x1 = __ldcs(&p1[row * NF4 + q]);
            float m0 = smA0[row];
            float m1 = smA1[row];
            a0.x = fmaf(m0, x0.x, a0.x);
            a0.y = fmaf(m0, x0.y, a0.y);
            a0.z = fmaf(m0, x0.z, a0.z);
            a0.w = fmaf(m0, x0.w, a0.w);
            a1.x = fmaf(m1, x1.x, a1.x);
            a1.y = fmaf(m1, x1.y, a1.y);
            a1.z = fmaf(m1, x1.z, a1.z);
            a1.w = fmaf(m1, x1.w, a1.w);
        }

        s0[t] = a0;
        s1[t] = a1;
    }

    // stash prefetched b1 mask
    {
        float mb = clip01(mbint);
        if (t < NROW) smB0[t] = mb;
        else          smB1[t - NROW] = mb;
    }
    __syncthreads();

    // ---- Phase 2: epilogue b0 (t<64) — overlaps b1 load issue by t>=64 ----
    if (t < NDIM) {
        const int qq = t >> 2;
        const int j  = t & 3;
        float u0 = 0.f, u1 = 0.f;
#pragma unroll
        for (int g = 0; g < 16; ++g) {
            const float* f0 = (const float*)&s0[g * NF4 + qq];
            const float* f1 = (const float*)&s1[g * NF4 + qq];
            u0 += f0[j];
            u1 += f1[j];
        }
        float prod = u0 * u1;
#pragma unroll
        for (int off = 16; off > 0; off >>= 1)
            prod += __shfl_xor_sync(0xFFFFFFFFu, prod, off);
        if ((t & 31) == 0)
            sdotA[t >> 5] = prod;
    }

    // ---- Phase 3: main loop batch b1 (masks already in smB) ----
    {
        const float4* p0 = V0 + (size_t)b1 * (NROW * NF4);
        const float4* p1 = V1 + (size_t)b1 * (NROW * NF4);

        float4 a0 = make_float4(0.f, 0.f, 0.f, 0.f);
        float4 a1 = make_float4(0.f, 0.f, 0.f, 0.f);

#pragma unroll
        for (int k = 0; k < ROWS_PER_THREAD; ++k) {
            const int row = r0 + k * 16;
            float4 x0 = __ldcs(&p0[row * NF4 + q]);
            float4 x1 = __ldcs(&p1[row * NF4 + q]);
            float m0 = smB0[row];
            float m1 = smB1[row];
            a0.x = fmaf(m0, x0.x, a0.x);
            a0.y = fmaf(m0, x0.y, a0.y);
            a0.z = fmaf(m0, x0.z, a0.z);
            a0.w = fmaf(m0, x0.w, a0.w);
            a1.x = fmaf(m1, x1.x, a1.x);
            a1.y = fmaf(m1, x1.y, a1.y);
            a1.z = fmaf(m1, x1.z, a1.z);
            a1.w = fmaf(m1, x1.w, a1.w);
        }

        // barrier: guarantees epilogue-b0 reads of s0/s1 and sdotA writes done
        __syncthreads();
        if (t == 0) out[b0] = sdotA[0] + sdotA[1];

        s0[t] = a0;
        s1[t] = a1;
    }
    __syncthreads();

    // ---- Phase 4: epilogue b1 ----
    if (t < NDIM) {
        const int qq = t >> 2;
        const int j  = t & 3;
        float u0 = 0.f, u1 = 0.f;
#pragma unroll
        for (int g = 0; g < 16; ++g) {
            const float* f0 = (const float*)&s0[g * NF4 + qq];
            const float* f1 = (const float*)&s1[g * NF4 + qq];
            u0 += f0[j];
            u1 += f1[j];
        }
        float prod = u0 * u1;
#pragma unroll
        for (int off = 16; off > 0; off >>= 1)
            prod += __shfl_xor_sync(0xFFFFFFFFu, prod, off);
        if ((t & 31) == 0)
            sdotB[t >> 5] = prod;
    }
    __syncthreads();

    if (t == 0)
        out[b1] = sdotB[0] + sdotB[1];
}

extern "C" void kernel_launch(void* const* d_in, const int* in_sizes, int n_in,
                              void* d_out, int out_size)
{
    const int*    VI0 = (const int*)d_in[0];
    const int*    VI1 = (const int*)d_in[1];
    const float4* V0  = (const float4*)d_in[2];
    const float4* V1  = (const float4*)d_in[3];
    float*        out = (float*)d_out;

    const int B    = in_sizes[0] / NROW;  // 4096
    const int half = B / 2;               // 2048 CTAs, 2 batches each
    fvi_kernel2<<<half, THREADS>>>(VI0, VI1, V0, V1, out, half);
}

// round 15
// speedup vs baseline: 1.0724x; 1.0258x over previous
#include <cuda_runtime.h>
#include <cuda_bf16.h>

// FeatureVectorInteractions: B=4096, N=128, D=64
// out[b] = < sum_i clip(VI0[b,i],0,1)*V0[b,i,:], sum_j clip(VI1[b,j],0,1)*V1[b,j,:] >
//
// Drain-tail minimization (lesson from grid=1024/2048 regressions: fewer,
// longer CTAs lose; the final-wave drain scales with T_CTA). Split each
// batch's dot across TWO CTAs by dimension halves — the dot is additive
// over d, so each CTA computes a 32-dim partial dot and atomicAdds it
// (exactly 2 commutative contributions -> bit-deterministic).
// grid = 2B = 8192 CTAs x 128 threads, T_CTA = half of baseline.
// Each CTA streams 2 x 16KB (columns [32h,32h+32) of V0[b], V1[b]).

#define NROW 128
#define THREADS 128
#define HF4 8            // float4s per half-row (32 floats / 4)
#define NF4 16           // float4s per full row

__device__ __forceinline__ float clip01(int v) {
    return (float)min(max(v, 0), 1);
}

__global__ void fvi_zero(float* __restrict__ out, int n)
{
    int i = blockIdx.x * blockDim.x + threadIdx.x;
    if (i < n) out[i] = 0.0f;
}

__global__ __launch_bounds__(THREADS, 16)
void fvi_dimsplit(const int* __restrict__ VI0,
                  const int* __restrict__ VI1,
                  const float4* __restrict__ V0,
                  const float4* __restrict__ V1,
                  float* __restrict__ out)
{
    const int b = blockIdx.x >> 1;        // batch
    const int h = blockIdx.x & 1;         // dim half: 0 -> d[0,32), 1 -> d[32,64)
    const int t = threadIdx.x;

    __shared__ float sm0[NROW], sm1[NROW];
    __shared__ float4 s0[THREADS], s1[THREADS];

    // masks: 128 threads load both rows' mask ints
    sm0[t] = clip01(VI0[b * NROW + t]);
    sm1[t] = clip01(VI1[b * NROW + t]);
    __syncthreads();

    const int q  = t & (HF4 - 1);   // float4 col within half: 0..7
    const int r0 = t >> 3;          // starting row-group: 0..15

    const float4* p0 = V0 + (size_t)b * (NROW * NF4) + h * HF4;
    const float4* p1 = V1 + (size_t)b * (NROW * NF4) + h * HF4;

    float4 a0 = make_float4(0.f, 0.f, 0.f, 0.f);
    float4 a1 = make_float4(0.f, 0.f, 0.f, 0.f);

#pragma unroll
    for (int k = 0; k < 8; ++k) {
        const int row = r0 + k * 16;
        float4 x0 = __ldcs(&p0[row * NF4 + q]);
        float4 x1 = __ldcs(&p1[row * NF4 + q]);
        float m0 = sm0[row];
        float m1 = sm1[row];
        a0.x = fmaf(m0, x0.x, a0.x);
        a0.y = fmaf(m0, x0.y, a0.y);
        a0.z = fmaf(m0, x0.z, a0.z);
        a0.w = fmaf(m0, x0.w, a0.w);
        a1.x = fmaf(m1, x1.x, a1.x);
        a1.y = fmaf(m1, x1.y, a1.y);
        a1.z = fmaf(m1, x1.z, a1.z);
        a1.w = fmaf(m1, x1.w, a1.w);
    }

    s0[t] = a0;
    s1[t] = a1;
    __syncthreads();

    // warp 0: dim d = lane (32 dims in this half). word idx = 32g + d -> conflict-free
    if (t < 32) {
        const int qq = t >> 2;   // float4 col 0..7
        const int j  = t & 3;
        float u0 = 0.f, u1 = 0.f;
#pragma unroll
        for (int g = 0; g < 16; ++g) {
            const float* f0 = (const float*)&s0[g * HF4 + qq];
            const float* f1 = (const float*)&s1[g * HF4 + qq];
            u0 += f0[j];
            u1 += f1[j];
        }
        float prod = u0 * u1;
#pragma unroll
        for (int off = 16; off > 0; off >>= 1)
            prod += __shfl_xor_sync(0xFFFFFFFFu, prod, off);
        if (t == 0)
            atomicAdd(&out[b], prod);   // exactly 2 adds per out[b]; commutative -> deterministic
    }
}

extern "C" void kernel_launch(void* const* d_in, const int* in_sizes, int n_in,
                              void* d_out, int out_size)
{
    const int*    VI0 = (const int*)d_in[0];
    const int*    VI1 = (const int*)d_in[1];
    const float4* V0  = (const float4*)d_in[2];
    const float4* V1  = (const float4*)d_in[3];
    float*        out = (float*)d_out;

    const int B = in_sizes[0] / NROW;   // 4096

    fvi_zero<<<(B + 255) / 256, 256>>>(out, B);
    fvi_dimsplit<<<B * 2, THREADS>>>(VI0, VI1, V0, V1, out);
}

// round 17
// speedup vs baseline: 1.1008x; 1.0265x over previous
#include <cuda_runtime.h>
#include <cuda_bf16.h>

// FeatureVectorInteractions: B=4096, N=128, D=64
// out[b] = < sum_i clip(VI0[b,i],0,1)*V0[b,i,:], sum_j clip(VI1[b,j],0,1)*V1[b,j,:] >
//
// Baseline structure (one batch per 256-thread CTA, grid=4096 — measured
// optimum of the wave/granularity trade across grid={1024,2048,4096,8192})
// with the prologue serialization removed: masks are loaded per-iteration
// via LDG with intra-warp address broadcast (2 rows/warp/iter -> 2 sectors,
// L1-cached), so there is NO barrier before the V stream starts. Single
// __syncthreads before the epilogue; warp 0 reduces both dim-halves.

#define NROW 128
#define NDIM 64
#define NF4  16            // float4s per row (64 floats / 4)
#define THREADS 256

__device__ __forceinline__ float clip01(int v) {
    return (float)min(max(v, 0), 1);
}

__global__ __launch_bounds__(THREADS, 8)
void fvi_kernel3(const int* __restrict__ VI0,
                 const int* __restrict__ VI1,
                 const float4* __restrict__ V0,
                 const float4* __restrict__ V1,
                 float* __restrict__ out)
{
    const int b = blockIdx.x;
    const int t = threadIdx.x;

    __shared__ float4 s0[THREADS], s1[THREADS];

    const int q  = t & (NF4 - 1);   // float4 column 0..15
    const int r0 = t >> 4;          // starting row-group 0..15

    const int*    vi0 = VI0 + b * NROW;
    const int*    vi1 = VI1 + b * NROW;
    const float4* p0  = V0 + (size_t)b * (NROW * NF4);
    const float4* p1  = V1 + (size_t)b * (NROW * NF4);

    float4 a0 = make_float4(0.f, 0.f, 0.f, 0.f);
    float4 a1 = make_float4(0.f, 0.f, 0.f, 0.f);

#pragma unroll
    for (int k = 0; k < 8; ++k) {
        const int row = r0 + k * 16;
        // masks via LDG broadcast: 16 lanes share each address -> 2 sectors/warp
        float m0 = clip01(__ldg(&vi0[row]));
        float m1 = clip01(__ldg(&vi1[row]));
        float4 x0 = p0[row * NF4 + q];
        float4 x1 = p1[row * NF4 + q];
        a0.x = fmaf(m0, x0.x, a0.x);
        a0.y = fmaf(m0, x0.y, a0.y);
        a0.z = fmaf(m0, x0.z, a0.z);
        a0.w = fmaf(m0, x0.w, a0.w);
        a1.x = fmaf(m1, x1.x, a1.x);
        a1.y = fmaf(m1, x1.y, a1.y);
        a1.z = fmaf(m1, x1.z, a1.z);
        a1.w = fmaf(m1, x1.w, a1.w);
    }

    s0[t] = a0;
    s1[t] = a1;
    __syncthreads();   // the only barrier

    // Epilogue: warp 0 reduces both dim-halves (dims d=t and d=t+32).
    // word index = 64g + d: per-access lanes hit distinct banks.
    if (t < 32) {
        const float* w0 = (const float*)s0;
        const float* w1 = (const float*)s1;
        float u0a = 0.f, u1a = 0.f, u0b = 0.f, u1b = 0.f;
#pragma unroll
        for (int g = 0; g < 16; ++g) {
            u0a += w0[g * 64 + t];
            u1a += w1[g * 64 + t];
            u0b += w0[g * 64 + t + 32];
            u1b += w1[g * 64 + t + 32];
        }
        float prod = u0a * u1a + u0b * u1b;
#pragma unroll
        for (int off = 16; off > 0; off >>= 1)
            prod += __shfl_xor_sync(0xFFFFFFFFu, prod, off);
        if (t == 0)
            out[b] = prod;
    }
}

extern "C" void kernel_launch(void* const* d_in, const int* in_sizes, int n_in,
                              void* d_out, int out_size)
{
    const int*    VI0 = (const int*)d_in[0];
    const int*    VI1 = (const int*)d_in[1];
    const float4* V0  = (const float4*)d_in[2];
    const float4* V1  = (const float4*)d_in[3];
    float*        out = (float*)d_out;

    const int B = in_sizes[0] / NROW;   // 4096
    fvi_kernel3<<<B, THREADS>>>(VI0, VI1, V0, V1, out);
}